// round 2
// baseline (speedup 1.0000x reference)
#include <cuda_runtime.h>
#include <math.h>

// ============================================================================
// SofaNetEllipse: three tiny scalar-input MLPs (1->256->256->2, tanh) + JVP.
// Strategy: the MLPs are smooth 1-D functions of u = pi*t. Evaluate them
// EXACTLY (fp32, analytic 1st+2nd derivatives) on a fine grid (stage 1),
// then cubic-Hermite interpolate per point and apply exact trig (stage 2).
// ============================================================================

#define G_NODES 1025
#define NBLK 16                    // grid nodes per stage-1 CTA
#define PI_F 3.14159265358979323846f
#define T_MAX 6.5f
#define H_T (13.0f / 1024.0f)      // node spacing in t
#define INV_H_T (1024.0f / 13.0f)
#define H_U (PI_F * H_T)           // node spacing in u

// Scratch (static __device__ globals: allocation-free per harness rules)
__device__ float g_W1T[3][256 * 256];       // transposed hidden weights [k][j]
__device__ float g_tab[18][G_NODES];        // row = f*3 + {0:val,1:d/du,2:d2/du2},
                                            // f = mlp*2 + out_component

// ----------------------------------------------------------------------------
// Transpose W1 (256x256 row-major [j][k]) -> g_W1T [k][j] for coalesced GEMM.
// ----------------------------------------------------------------------------
__global__ void transpose_w1_kernel(const float* __restrict__ A0,
                                    const float* __restrict__ A1,
                                    const float* __restrict__ A2) {
    __shared__ float tile[32][33];
    int m = blockIdx.z;
    const float* src = (m == 0) ? A0 : (m == 1) ? A1 : A2;
    float* dst = g_W1T[m];
    int bx = blockIdx.x * 32, by = blockIdx.y * 32;
    int tx = threadIdx.x, ty = threadIdx.y;
    #pragma unroll
    for (int i = 0; i < 32; i += 8)
        tile[ty + i][tx] = src[(by + ty + i) * 256 + bx + tx];
    __syncthreads();
    #pragma unroll
    for (int i = 0; i < 32; i += 8)
        dst[(bx + ty + i) * 256 + by + tx] = tile[tx][ty + i];
}

// ----------------------------------------------------------------------------
// Stage 1: exact MLP eval (value, u-deriv, u-2nd-deriv) at grid nodes.
// One CTA = (one MLP m, block of NBLK nodes). 256 threads.
// Smem layout is K-MAJOR: Xs[k*48 + c], c = nodeLocal*3 + stream. This makes
// the GEMM inner-loop LDS conflict-free (banks (3*tcol) mod 32 all distinct)
// and, critically, cannot alias across columns (previous pitch bug).
// ----------------------------------------------------------------------------
__global__ __launch_bounds__(256) void stage1_kernel(
    const float* __restrict__ W0a, const float* __restrict__ b0a,
    const float* __restrict__ b1a, const float* __restrict__ W2a,
    const float* __restrict__ b2a,
    const float* __restrict__ W0k, const float* __restrict__ b0k,
    const float* __restrict__ b1k, const float* __restrict__ W2k,
    const float* __restrict__ b2k,
    const float* __restrict__ W0s, const float* __restrict__ b0s,
    const float* __restrict__ b1s, const float* __restrict__ W2s,
    const float* __restrict__ b2s) {

    __shared__ float Xs[256 * 48];   // k-major: Xs[k*48 + c]  (48 KB exactly)

    const int m = blockIdx.y;
    const int nb0 = blockIdx.x * NBLK;
    const int tid = threadIdx.x;

    const float* W0 = (m == 0) ? W0a : (m == 1) ? W0k : W0s;
    const float* b0 = (m == 0) ? b0a : (m == 1) ? b0k : b0s;
    const float* b1 = (m == 0) ? b1a : (m == 1) ? b1k : b1s;
    const float* W2 = (m == 0) ? W2a : (m == 1) ? W2k : W2s;
    const float* b2 = (m == 0) ? b2a : (m == 1) ? b2k : b2s;

    // ---- Layer 0: thread = neuron tid, loop over NBLK nodes ----
    {
        const float w0 = W0[tid];
        const float bb = b0[tid];
        float* xrow = &Xs[tid * 48];
        #pragma unroll
        for (int n = 0; n < NBLK; n++) {
            int node = nb0 + n;
            if (node > G_NODES - 1) node = G_NODES - 1;   // pad last block
            float tn = -T_MAX + H_T * (float)node;
            float u = PI_F * tn;
            float e = tanhf(w0 * u + bb);
            float g = 1.0f - e * e;
            float d1 = g * w0;
            float d2 = -2.0f * e * d1 * w0;
            xrow[n * 3 + 0] = e;
            xrow[n * 3 + 1] = d1;
            xrow[n * 3 + 2] = d2;
        }
    }
    __syncthreads();

    // ---- Layer 1 GEMM: thread tile = 16 rows x (1 node * 3 streams) ----
    const int tcol = tid & 15;        // node within block
    const int trow = tid >> 4;        // row group
    const int r0 = trow * 16;
    const int c0 = tcol * 3;

    float acc[16][3];
    #pragma unroll
    for (int i = 0; i < 16; i++) { acc[i][0] = 0.f; acc[i][1] = 0.f; acc[i][2] = 0.f; }

    const float* Wt = &g_W1T[m][0];
    #pragma unroll 4
    for (int k = 0; k < 256; k++) {
        float x0 = Xs[k * 48 + c0 + 0];
        float x1 = Xs[k * 48 + c0 + 1];
        float x2 = Xs[k * 48 + c0 + 2];
        const float4* wr = reinterpret_cast<const float4*>(Wt + k * 256 + r0);
        #pragma unroll
        for (int q = 0; q < 4; q++) {
            float4 w = __ldg(&wr[q]);
            acc[q * 4 + 0][0] += w.x * x0; acc[q * 4 + 0][1] += w.x * x1; acc[q * 4 + 0][2] += w.x * x2;
            acc[q * 4 + 1][0] += w.y * x0; acc[q * 4 + 1][1] += w.y * x1; acc[q * 4 + 1][2] += w.y * x2;
            acc[q * 4 + 2][0] += w.z * x0; acc[q * 4 + 2][1] += w.z * x1; acc[q * 4 + 2][2] += w.z * x2;
            acc[q * 4 + 3][0] += w.w * x0; acc[q * 4 + 3][1] += w.w * x1; acc[q * 4 + 3][2] += w.w * x2;
        }
    }

    // ---- Epilogue (tanh + JVP chain) + Layer 2 partial dot products ----
    float part[2][3] = {{0.f, 0.f, 0.f}, {0.f, 0.f, 0.f}};
    #pragma unroll
    for (int i = 0; i < 16; i++) {
        int r = r0 + i;
        float z   = acc[i][0] + b1[r];
        float zp  = acc[i][1];
        float zpp = acc[i][2];
        float h = tanhf(z);
        float g = 1.0f - h * h;
        float hp = g * zp;
        float hpp = g * zpp - 2.0f * h * hp * zp;
        float wa = W2[r];          // W2[0][r]
        float wb = W2[256 + r];    // W2[1][r]
        part[0][0] += wa * h;  part[0][1] += wa * hp;  part[0][2] += wa * hpp;
        part[1][0] += wb * h;  part[1][1] += wb * hp;  part[1][2] += wb * hpp;
    }

    // ---- Cross-thread reduction over the 16 row-groups (smem, deterministic)
    __syncthreads();   // done with Xs; reuse as reduction buffer
    // layout: red[tcol*96 + q*16 + trow], q = o*3 + kind
    #pragma unroll
    for (int o = 0; o < 2; o++)
        #pragma unroll
        for (int kd = 0; kd < 3; kd++)
            Xs[tcol * 96 + (o * 3 + kd) * 16 + trow] = part[o][kd];
    __syncthreads();

    if (tid < 96) {
        int nodeLoc = tid / 6;
        int q = tid % 6;
        int o = q / 3, kd = q % 3;
        float s = 0.f;
        #pragma unroll
        for (int w = 0; w < 16; w++) s += Xs[nodeLoc * 96 + q * 16 + w];
        int node = nb0 + nodeLoc;
        if (node < G_NODES) {
            if (kd == 0) s += b2[o];
            g_tab[(m * 2 + o) * 3 + kd][node] = s;
        }
    }
}

// ----------------------------------------------------------------------------
// Stage 2: per-point cubic Hermite interpolation + exact trig + product rule.
// Values interpolate with (f, f_u); u-derivatives with (f_u, f_uu).
// ----------------------------------------------------------------------------
__global__ __launch_bounds__(256) void stage2_kernel(const float* __restrict__ t_in,
                                                     float* __restrict__ out, int N) {
    int i = blockIdx.x * blockDim.x + threadIdx.x;
    if (i >= N) return;

    float tv = t_in[i];
    out[i]         = tv * (PI_F * 0.5f);   // alpha
    out[3 * N + i] = PI_F * 0.5f;          // alpha'

    float tc = fminf(fmaxf(tv, -T_MAX), T_MAX);
    float s = (tc + T_MAX) * INV_H_T;
    int j = (int)floorf(s);
    j = max(0, min(j, G_NODES - 2));
    float f = s - (float)j;

    float f2 = f * f, f3 = f2 * f;
    float h00 = 2.f * f3 - 3.f * f2 + 1.f;
    float h01 = -2.f * f3 + 3.f * f2;
    float h10 = (f3 - 2.f * f2 + f) * H_U;
    float h11 = (f3 - f2) * H_U;

    float vals[6], ders[6];
    #pragma unroll
    for (int fn = 0; fn < 6; fn++) {
        const float* V  = g_tab[fn * 3 + 0];
        const float* D  = g_tab[fn * 3 + 1];
        const float* DD = g_tab[fn * 3 + 2];
        float vL = V[j],  vR = V[j + 1];
        float dL = D[j],  dR = D[j + 1];
        float eL = DD[j], eR = DD[j + 1];
        vals[fn] = h00 * vL + h01 * vR + h10 * dL + h11 * dR;
        ders[fn] = h00 * dL + h01 * dR + h10 * eL + h11 * eR;
    }

    float u = PI_F * tv;
    float sn, cs;
    sincosf(u, &sn, &cs);
    float cm1 = cs - 1.0f;

    float a  = vals[0], b  = vals[1], kx  = vals[2], ky  = vals[3], sx  = vals[4], sy  = vals[5];
    float au = ders[0], bu = ders[1], kxu = ders[2], kyu = ders[3], sxu = ders[4], syu = ders[5];

    float xp = a * cm1 * kx + sx;
    float yp = b * sn * ky + sy;
    float xpu = (au * cm1 - a * sn) * kx + a * cm1 * kxu + sxu;
    float ypu = (bu * sn + b * cs) * ky + b * sn * kyu + syu;

    out[1 * N + i] = xp;
    out[2 * N + i] = yp;
    out[4 * N + i] = PI_F * xpu;
    out[5 * N + i] = PI_F * ypu;
}

// ----------------------------------------------------------------------------
// Launch. Inputs (metadata order):
//  0:t  1:W_ab0 2:b_ab0 3:W_ab1 4:b_ab1 5:W_ab2 6:b_ab2
//  7:W_kxy0 8:b_kxy0 9:W_kxy1 10:b_kxy1 11:W_kxy2 12:b_kxy2
// 13:W_sxy0 14:b_sxy0 15:W_sxy1 16:b_sxy1 17:W_sxy2 18:b_sxy2
// Output: [alpha | xp | yp | alpha' | xp' | yp'] each of length N.
// ----------------------------------------------------------------------------
extern "C" void kernel_launch(void* const* d_in, const int* in_sizes, int n_in,
                              void* d_out, int out_size) {
    const float* t     = (const float*)d_in[0];
    const float* W_ab0 = (const float*)d_in[1];
    const float* b_ab0 = (const float*)d_in[2];
    const float* W_ab1 = (const float*)d_in[3];
    const float* b_ab1 = (const float*)d_in[4];
    const float* W_ab2 = (const float*)d_in[5];
    const float* b_ab2 = (const float*)d_in[6];
    const float* W_k0  = (const float*)d_in[7];
    const float* b_k0  = (const float*)d_in[8];
    const float* W_k1  = (const float*)d_in[9];
    const float* b_k1  = (const float*)d_in[10];
    const float* W_k2  = (const float*)d_in[11];
    const float* b_k2  = (const float*)d_in[12];
    const float* W_s0  = (const float*)d_in[13];
    const float* b_s0  = (const float*)d_in[14];
    const float* W_s1  = (const float*)d_in[15];
    const float* b_s1  = (const float*)d_in[16];
    const float* W_s2  = (const float*)d_in[17];
    const float* b_s2  = (const float*)d_in[18];

    int N = in_sizes[0];
    float* out = (float*)d_out;

    transpose_w1_kernel<<<dim3(8, 8, 3), dim3(32, 8)>>>(W_ab1, W_k1, W_s1);

    int nblocks = (G_NODES + NBLK - 1) / NBLK;   // 65
    stage1_kernel<<<dim3(nblocks, 3), 256>>>(
        W_ab0, b_ab0, b_ab1, W_ab2, b_ab2,
        W_k0,  b_k0,  b_k1,  W_k2,  b_k2,
        W_s0,  b_s0,  b_s1,  W_s2,  b_s2);

    stage2_kernel<<<(N + 255) / 256, 256>>>(t, out, N);
}